// round 16
// baseline (speedup 1.0000x reference)
#include <cuda_runtime.h>
#include <math.h>
#include <stdint.h>

#define B_   4
#define S_   2048
#define DM   1024
#define H_   8
#define DK   128
#define DC   32
#define DHR  32
#define BS_  (B_*S_)        // 8192

// ---------------- scratch (device globals) ----------------------------------
__device__ float g_cq  [BS_*DC];               // fp32
__device__ float g_kt  [BS_*64];               // K~ pair-permuted cols, rounded
__device__ float g_cvT [BS_*DC];               // C^T tiles [tile][col][64 rows perm]
__device__ float g_qt  [(size_t)B_*H_*S_*64];  // Q~ permuted, PRE-SCALED by scale*log2e, rounded
__device__ float g_ot  [(size_t)BS_*H_*32];    // O~ [B,S,H*32], rounded
__device__ float g_M   [H_*DC*DC];
__device__ float g_m   [H_*DC];
__device__ float g_weff[256*DM];               // rounded
__device__ float g_beff[DM];
__device__ float g_wdown[1024*96];             // [Wdq|Wdkv|Wkr], rounded

// ---------------- helpers ----------------------------------------------------
__device__ __forceinline__ float to_tf32(float x) {
    uint32_t u;
    asm("cvt.rna.tf32.f32 %0, %1;" : "=r"(u) : "f"(x));
    return __uint_as_float(u);
}
__device__ __forceinline__ int perm8(int c) {
    return ((c & 3) << 1) | ((c >> 2) & 1);
}
__device__ __forceinline__ int ppos(int c) {
    return (c & ~7) | perm8(c & 7);
}
__device__ __forceinline__ void mma_tf32(float* d, const float* a, const float* b) {
    asm("mma.sync.aligned.m16n8k8.row.col.f32.tf32.tf32.f32 "
        "{%0,%1,%2,%3}, {%4,%5,%6,%7}, {%8,%9}, {%0,%1,%2,%3};"
        : "+f"(d[0]), "+f"(d[1]), "+f"(d[2]), "+f"(d[3])
        : "r"(__float_as_uint(a[0])), "r"(__float_as_uint(a[1])),
          "r"(__float_as_uint(a[2])), "r"(__float_as_uint(a[3])),
          "r"(__float_as_uint(b[0])), "r"(__float_as_uint(b[1])));
}
__device__ __forceinline__ void cp_async16(uint32_t saddr, const void* gptr) {
    asm volatile("cp.async.cg.shared.global [%0], [%1], 16;"
                 :: "r"(saddr), "l"(gptr));
}
#define CP_COMMIT()  asm volatile("cp.async.commit_group;")
#define CP_WAIT1()   asm volatile("cp.async.wait_group 1;")

// ---------------------------------------------------------------------------
// Launch 1: merged prep. blocks 0..7: M_h,m_h (smem-staged); 8..19: wdown;
// 20..83: W_eff; 84..115: b_eff.
// ---------------------------------------------------------------------------
__global__ void __launch_bounds__(256) prep_kernel(
    const float* __restrict__ Wuq, const float* __restrict__ buq,
    const float* __restrict__ Wuk,
    const float* __restrict__ Wdq, const float* __restrict__ Wdkv,
    const float* __restrict__ Wkr,
    const float* __restrict__ Wuv, const float* __restrict__ buv,
    const float* __restrict__ Wo,  const float* __restrict__ bo)
{
    const int tid = threadIdx.x;
    const int bx  = blockIdx.x;
    if (bx < 8) {
        __shared__ float wq_s[32*128];
        __shared__ float wk_s[32*128];
        const int h = bx;
#pragma unroll
        for (int i = 0; i < 4; i++) {
            int idx4 = tid + i*256;
            int r = idx4 >> 5, c4 = idx4 & 31;
            *(float4*)(wq_s + r*128 + c4*4) =
                *(const float4*)(Wuq + (size_t)r*DM + h*DK + c4*4);
            *(float4*)(wk_s + r*128 + c4*4) =
                *(const float4*)(Wuk + (size_t)r*DM + h*DK + c4*4);
        }
        __syncthreads();
        for (int idx = tid; idx < DC*DC; idx += 256) {
            int c = idx >> 5, i = idx & 31;
            float s = 0.f;
#pragma unroll 8
            for (int d = 0; d < DK; d++) s += wq_s[c*128 + d]*wk_s[i*128 + d];
            g_M[h*DC*DC + idx] = s;
        }
        if (tid < DC) {
            float s = 0.f;
#pragma unroll 8
            for (int d = 0; d < DK; d++) s += buq[h*DK + d]*wk_s[tid*128 + d];
            g_m[h*DC + tid] = s;
        }
    } else if (bx < 20) {
        int base = (bx - 8)*8192 + tid;
#pragma unroll
        for (int i = 0; i < 32; i++) {
            int idx = base + i*256;
            int k = idx / 96, c = idx - 96*k;
            float v;
            if (c < 32)      v = Wdq [k*32 + c];
            else if (c < 64) v = Wdkv[k*32 + (c-32)];
            else             v = Wkr [k*32 + (c-64)];
            g_wdown[idx] = to_tf32(v);
        }
    } else if (bx < 84) {
        const int h = (bx-20) >> 3, jt = (bx-20) & 7;
        const int i = tid >> 3, jg = tid & 7;
        const int j0 = jt*128 + jg*16;
        float acc[16];
#pragma unroll
        for (int k = 0; k < 16; k++) acc[k] = 0.f;
        for (int d = 0; d < DK; d++) {
            float wuv = Wuv[i*DM + h*DK + d];
            const float* wo = Wo + (size_t)(h*DK + d)*DM + j0;
#pragma unroll
            for (int k = 0; k < 16; k++) acc[k] += wuv*wo[k];
        }
#pragma unroll
        for (int k = 0; k < 16; k++)
            g_weff[(size_t)(h*32 + i)*DM + j0 + k] = to_tf32(acc[k]);
    } else {
        __shared__ float red[8][32];
        const int j0 = (bx - 84)*32;
        const int jj = tid & 31, ks = tid >> 5;
        float s = 0.f;
        const int k0 = ks*128;
        for (int k = 0; k < 128; k++)
            s += buv[k0 + k]*Wo[(size_t)(k0 + k)*DM + j0 + jj];
        red[ks][jj] = s;
        __syncthreads();
        if (ks == 0) {
            float acc = bo[j0 + jj];
#pragma unroll
            for (int r = 0; r < 8; r++) acc += red[r][jj];
            g_beff[j0 + jj] = acc;
        }
    }
}

// ---------------------------------------------------------------------------
// Launch 2: down projections via tf32 mma, 3-stage pipeline, 64-row tiles.
// ---------------------------------------------------------------------------
#define DSA 36
#define DSB 104
#define DABUF (64*DSA)
#define DBBUF (32*DSB)
#define DOWN_SMEM_FLOATS (3*DABUF + 3*DBBUF)

__global__ void __launch_bounds__(256) down_proj_kernel(
    const float* __restrict__ h,
    const float* __restrict__ bdq, const float* __restrict__ bdkv,
    const float* __restrict__ bkr)
{
    extern __shared__ float sm[];
    float* a_s = sm;
    float* b_s = sm + 3*DABUF;
    const uint32_t smb = (uint32_t)__cvta_generic_to_shared(sm);

    const int tid  = threadIdx.x;
    const int lane = tid & 31;
    const int warp = tid >> 5;
    const int gid  = lane >> 2, tig = lane & 3;
    const int wm = warp >> 1, wn = warp & 1;
    const int row0 = blockIdx.x * 64;

    auto issue_ab = [&](int s, int kc) {
        const uint32_t adst = smb + (uint32_t)(s*DABUF)*4u;
        const uint32_t bdst = smb + (uint32_t)(3*DABUF + s*DBBUF)*4u;
#pragma unroll
        for (int i = 0; i < 2; i++) {
            int idx4 = tid + i*256;
            int r = idx4 >> 3, c4 = idx4 & 7;
            cp_async16(adst + (uint32_t)(r*DSA + c4*4)*4u,
                       h + (size_t)(row0+r)*DM + kc*32 + c4*4);
        }
#pragma unroll
        for (int i = 0; i < 3; i++) {
            int idx4 = tid + i*256;
            int r = idx4 / 24, cc = idx4 - 24*r;
            cp_async16(bdst + (uint32_t)(r*DSB + cc*4)*4u,
                       g_wdown + (size_t)(kc*32+r)*96 + cc*4);
        }
    };

    float acc[6][4];
#pragma unroll
    for (int n = 0; n < 6; n++)
#pragma unroll
        for (int j = 0; j < 4; j++) acc[n][j] = 0.f;

    issue_ab(0, 0); CP_COMMIT();
    issue_ab(1, 1); CP_COMMIT();

    for (int kc = 0; kc < 32; kc++) {
        CP_WAIT1();
        __syncthreads();
        if (kc + 2 < 32) issue_ab((kc + 2) % 3, kc + 2);
        CP_COMMIT();
        const float* ap = a_s + (kc % 3)*DABUF;
        const float* bp = b_s + (kc % 3)*DBBUF;

#pragma unroll
        for (int ks = 0; ks < 4; ks++) {
            const int c0 = ks*8 + tig;
            float a0[4];
            int ra = wm*16 + gid;
            a0[0] = ap[ ra      *DSA + c0    ];
            a0[1] = ap[(ra+8)   *DSA + c0    ];
            a0[2] = ap[ ra      *DSA + c0 + 4];
            a0[3] = ap[(ra+8)   *DSA + c0 + 4];
#pragma unroll
            for (int nt = 0; nt < 6; nt++) {
                float b[2];
                int nb = wn*48 + nt*8 + gid;
                b[0] = bp[(ks*8 + tig    )*DSB + nb];
                b[1] = bp[(ks*8 + tig + 4)*DSB + nb];
                mma_tf32(acc[nt], a0, b);
            }
        }
    }

    {
        int rbase = row0 + wm*16 + gid;
#pragma unroll
        for (int nt = 0; nt < 6; nt++) {
            int cc = wn*48 + nt*8 + 2*tig;
#pragma unroll
            for (int half = 0; half < 2; half++) {
                int rr = rbase + half*8;
#pragma unroll
                for (int e = 0; e < 2; e++) {
                    int col = cc + e;
                    float v = acc[nt][half*2 + e];
                    if (col < 32) {
                        g_cq[rr*32 + col] = v + bdq[col];
                    } else if (col < 64) {
                        float cv = to_tf32(v + bdkv[col-32]);
                        g_kt[rr*64 + ppos(col-32)] = cv;
                        int t = rr >> 6, lr = rr & 63;
                        g_cvT[((size_t)t*32 + (col-32))*64 + ppos(lr)] = cv;
                    } else {
                        g_kt[rr*64 + 32 + ppos(col-64)] =
                            to_tf32(v + bkr[col-64]);
                    }
                }
            }
        }
    }
}

// ---------------------------------------------------------------------------
// Launch 3: Q~ = (scale*log2e) * [c_q@M_h+m_h | c_q@W_QR_h+b_QR_h], permuted.
// Weights transposed in smem (k-contiguous) -> float4 dot products.
// ---------------------------------------------------------------------------
__global__ void __launch_bounds__(256) q_proj_kernel(
    const float* __restrict__ Wqr, const float* __restrict__ bqr)
{
    __shared__ float w2_s[64*36];     // [col][k], stride 36 (144B, 16B-multiple)
    __shared__ float c_s[64*32];
    __shared__ float bias_s[64];

    const int tid  = threadIdx.x;
    const int hh   = blockIdx.y;
    const int row0 = blockIdx.x * 64;
    const float pres = 0.07905694150420948f * 1.4426950408889634f; // scale*log2e

#pragma unroll
    for (int i = 0; i < 8; i++) {
        int idx = tid + i*256;
        int col = idx >> 5, k = idx & 31;
        w2_s[col*36 + k] = (col < 32) ? g_M[hh*DC*DC + k*32 + col]
                                      : Wqr[k*256 + hh*32 + (col-32)];
    }
    if (tid < 64)
        bias_s[tid] = (tid < 32) ? g_m[hh*DC + tid] : bqr[hh*32 + tid - 32];
#pragma unroll
    for (int i = 0; i < 8; i++) {
        int idx = tid + i*256;
        c_s[idx] = g_cq[row0*32 + idx];
    }
    __syncthreads();

    const int col = tid & 63, rg = tid >> 6;
    const int pcol = ppos(col);
    float w[8][4];
#pragma unroll
    for (int q = 0; q < 8; q++)
        *(float4*)w[q] = *(const float4*)(w2_s + col*36 + q*4);
    const float bias = bias_s[col];

    for (int rr = 0; rr < 16; rr++) {
        int r = rg*16 + rr;
        float acc = bias;
#pragma unroll
        for (int q = 0; q < 8; q++) {
            float4 cv = *(const float4*)(c_s + r*32 + q*4);
            acc += cv.x*w[q][0] + cv.y*w[q][1] + cv.z*w[q][2] + cv.w*w[q][3];
        }
        int row = row0 + r;
        int bb = row >> 11, ss = row & 2047;
        g_qt[((size_t)(bb*H_ + hh)*S_ + ss)*64 + pcol] = to_tf32(acc * pres);
    }
}

// ---------------------------------------------------------------------------
// Launch 4 (PROFILED): absorbed flash attention, exp2-based softmax.
// ---------------------------------------------------------------------------
#define SKT 72
#define SCT 72
#define KT_FL (64*SKT)
#define CT_FL (32*SCT)
#define QBUF_FL (256*SKT)
#define ATTN_SMEM_FLOATS (QBUF_FL + 3*KT_FL + 3*CT_FL)

__global__ void __launch_bounds__(512, 1) attn_kernel()
{
    extern __shared__ float sm[];
    float* qbuf = sm;
    float* kbuf = sm + QBUF_FL;
    float* cbuf = kbuf + 3*KT_FL;
    const uint32_t smb = (uint32_t)__cvta_generic_to_shared(sm);

    const int tid  = threadIdx.x;
    const int lane = tid & 31;
    const int warp = tid >> 5;
    const int gid  = lane >> 2;
    const int tig  = lane & 3;
    const int bh   = blockIdx.y;
    const int bb   = bh >> 3, hh = bh & 7;
    const int q0   = blockIdx.x * 256;

    const float* qg = g_qt + ((size_t)bh*S_ + q0)*64;
    const float* kg = g_kt + (size_t)bb*S_*64;
    const float* cg = g_cvT + (size_t)bb*(S_/64)*2048;

#pragma unroll
    for (int i = 0; i < 8; i++) {
        int idx4 = tid + i*512;
        int r = idx4 >> 4, c4 = idx4 & 15;
        float4 v = *(const float4*)(qg + (size_t)r*64 + c4*4);
        *(float4*)(qbuf + r*SKT + c4*4) = v;
    }
    __syncthreads();

    const int r0 = warp*16 + gid;
    float qf[8][4];
#pragma unroll
    for (int kb = 0; kb < 8; kb++) {
        float2 f0 = *(const float2*)(qbuf +  r0   *SKT + kb*8 + 2*tig);
        float2 f1 = *(const float2*)(qbuf + (r0+8)*SKT + kb*8 + 2*tig);
        qf[kb][0] = f0.x; qf[kb][1] = f1.x; qf[kb][2] = f0.y; qf[kb][3] = f1.y;
    }

    auto issue_kv = [&](int s, int t) {
        const float* ksrc = kg + (size_t)t*64*64;
        const float* csrc = cg + (size_t)t*2048;
        const uint32_t kdst = smb + (uint32_t)(QBUF_FL + s*KT_FL)*4u;
        const uint32_t cdst = smb + (uint32_t)(QBUF_FL + 3*KT_FL + s*CT_FL)*4u;
#pragma unroll
        for (int i = 0; i < 2; i++) {
            int idx4 = tid + i*512;
            int r = idx4 >> 4, c4 = idx4 & 15;
            cp_async16(kdst + (uint32_t)(r*SKT + c4*4)*4u, ksrc + r*64 + c4*4);
        }
        {
            int c = tid >> 4, rg = tid & 15;
            cp_async16(cdst + (uint32_t)(c*SCT + rg*4)*4u, csrc + c*64 + rg*4);
        }
    };

    issue_kv(0, 0); CP_COMMIT();
    issue_kv(1, 1); CP_COMMIT();

    float m0 = -1e30f, m1 = -1e30f, l0 = 0.f, l1 = 0.f;
    float o[4][4];
#pragma unroll
    for (int i = 0; i < 4; i++)
#pragma unroll
        for (int j = 0; j < 4; j++) o[i][j] = 0.f;

    const int srcA = (lane & ~3) + (tig >> 1);
    const int srcB = srcA + 2;
    const bool odd = (tig & 1);

    for (int kt = 0; kt < S_/64; kt++) {
        CP_WAIT1();
        __syncthreads();
        if (kt + 2 < S_/64) issue_kv((kt + 2) % 3, kt + 2);
        CP_COMMIT();
        const float* ks = kbuf + (kt % 3)*KT_FL;
        const float* cs = cbuf + (kt % 3)*CT_FL;

        float sa[8][4];
#pragma unroll
        for (int n = 0; n < 8; n++)
#pragma unroll
            for (int j = 0; j < 4; j++) sa[n][j] = 0.f;

#pragma unroll
        for (int kb = 0; kb < 8; kb++) {
#pragma unroll
            for (int nt = 0; nt < 8; nt++) {
                float2 bv = *(const float2*)(ks + (nt*8+gid)*SKT + kb*8 + 2*tig);
                float b[2] = {bv.x, bv.y};
                mma_tf32(sa[nt], qf[kb], b);
            }
        }

        float mx0 = -1e30f, mx1 = -1e30f;
#pragma unroll
        for (int n = 0; n < 8; n++) {
            mx0 = fmaxf(mx0, fmaxf(sa[n][0], sa[n][1]));
            mx1 = fmaxf(mx1, fmaxf(sa[n][2], sa[n][3]));
        }
        mx0 = fmaxf(mx0, __shfl_xor_sync(0xffffffffu, mx0, 1));
        mx0 = fmaxf(mx0, __shfl_xor_sync(0xffffffffu, mx0, 2));
        mx1 = fmaxf(mx1, __shfl_xor_sync(0xffffffffu, mx1, 1));
        mx1 = fmaxf(mx1, __shfl_xor_sync(0xffffffffu, mx1, 2));

        float nm0 = fmaxf(m0, mx0), nm1 = fmaxf(m1, mx1);
        float al0 = exp2f(m0 - nm0), al1 = exp2f(m1 - nm1);
        m0 = nm0; m1 = nm1;

#pragma unroll
        for (int n = 0; n < 4; n++) {
            o[n][0] *= al0; o[n][1] *= al0;
            o[n][2] *= al1; o[n][3] *= al1;
        }

        float rs0 = 0.f, rs1 = 0.f;
#pragma unroll
        for (int kb = 0; kb < 8; kb++) {
            float p00 = exp2f(sa[kb][0] - nm0);
            float p01 = exp2f(sa[kb][1] - nm0);
            float p10 = exp2f(sa[kb][2] - nm1);
            float p11 = exp2f(sa[kb][3] - nm1);
            rs0 += p00 + p01; rs1 += p10 + p11;

            float q00A = __shfl_sync(0xffffffffu, p00, srcA);
            float q01A = __shfl_sync(0xffffffffu, p01, srcA);
            float q00B = __shfl_sync(0xffffffffu, p00, srcB);
            float q01B = __shfl_sync(0xffffffffu, p01, srcB);
            float q10A = __shfl_sync(0xffffffffu, p10, srcA);
            float q11A = __shfl_sync(0xffffffffu, p11, srcA);
            float q10B = __shfl_sync(0xffffffffu, p10, srcB);
            float q11B = __shfl_sync(0xffffffffu, p11, srcB);

            float a[4];
            a[0] = to_tf32(odd ? q01A : q00A);
            a[1] = to_tf32(odd ? q11A : q10A);
            a[2] = to_tf32(odd ? q01B : q00B);
            a[3] = to_tf32(odd ? q11B : q10B);
#pragma unroll
            for (int nt = 0; nt < 4; nt++) {
                float2 bv = *(const float2*)(cs + (nt*8+gid)*SCT + kb*8 + 2*tig);
                float b[2] = {bv.x, bv.y};
                mma_tf32(o[nt], a, b);
            }
        }
        rs0 += __shfl_xor_sync(0xffffffffu, rs0, 1);
        rs0 += __shfl_xor_sync(0xffffffffu, rs0, 2);
        rs1 += __shfl_xor_sync(0xffffffffu, rs1, 1);
        rs1 += __shfl_xor_sync(0xffffffffu, rs1, 2);
        l0 = l0*al0 + rs0; l1 = l1*al1 + rs1;
    }

    const float inv0 = 1.f / l0, inv1 = 1.f / l1;
    const int s0 = q0 + r0;
    float* op0 = g_ot + ((size_t)(bb*S_ + s0    )*H_ + hh)*32;
    float* op1 = g_ot + ((size_t)(bb*S_ + s0 + 8)*H_ + hh)*32;
#pragma unroll
    for (int nt = 0; nt < 4; nt++) {
        int col = nt*8 + 2*tig;
        *(float2*)(op0 + col) = make_float2(to_tf32(o[nt][0]*inv0), to_tf32(o[nt][1]*inv0));
        *(float2*)(op1 + col) = make_float2(to_tf32(o[nt][2]*inv1), to_tf32(o[nt][3]*inv1));
    }
}

// ---------------------------------------------------------------------------
// Launch 5: out = O~[8192x256] @ W_eff[256x1024] + b_eff, 3-stage pipeline
// ---------------------------------------------------------------------------
#define SA 36
#define SB 136
#define ABUF_FL (128*SA)
#define BBUF_FL (32*SB)
#define OUT_SMEM_FLOATS (3*ABUF_FL + 3*BBUF_FL)

__global__ void __launch_bounds__(256) out_proj_kernel(float* __restrict__ out)
{
    extern __shared__ float sm[];
    float* a_s = sm;
    float* b_s = sm + 3*ABUF_FL;
    const uint32_t smb = (uint32_t)__cvta_generic_to_shared(sm);

    const int tid  = threadIdx.x;
    const int lane = tid & 31;
    const int warp = tid >> 5;
    const int gid  = lane >> 2, tig = lane & 3;
    const int wm = warp >> 1, wn = warp & 1;
    const int col0 = blockIdx.x * 128;
    const int row0 = blockIdx.y * 128;

    auto issue_ab = [&](int s, int kc) {
        const uint32_t adst = smb + (uint32_t)(s*ABUF_FL)*4u;
        const uint32_t bdst = smb + (uint32_t)(3*ABUF_FL + s*BBUF_FL)*4u;
#pragma unroll
        for (int i = 0; i < 4; i++) {
            int idx4 = tid + i*256;
            int r = idx4 >> 3, c4 = idx4 & 7;
            cp_async16(adst + (uint32_t)(r*SA + c4*4)*4u,
                       g_ot + (size_t)(row0+r)*256 + kc*32 + c4*4);
        }
#pragma unroll
        for (int i = 0; i < 4; i++) {
            int idx4 = tid + i*256;
            int r = idx4 >> 5, c4 = idx4 & 31;
            cp_async16(bdst + (uint32_t)(r*SB + c4*4)*4u,
                       g_weff + (size_t)(kc*32+r)*DM + col0 + c4*4);
        }
    };

    float acc[2][8][4];
#pragma unroll
    for (int im = 0; im < 2; im++)
#pragma unroll
        for (int n = 0; n < 8; n++)
#pragma unroll
            for (int j = 0; j < 4; j++) acc[im][n][j] = 0.f;

    issue_ab(0, 0); CP_COMMIT();
    issue_ab(1, 1); CP_COMMIT();

    for (int kc = 0; kc < 8; kc++) {
        CP_WAIT1();
        __syncthreads();
        if (kc + 2 < 8) issue_ab((kc + 2) % 3, kc + 2);
        CP_COMMIT();
        const float* ap = a_s + (kc % 3)*ABUF_FL;
        const float* bp = b_s + (kc % 3)*BBUF_FL;

#pragma unroll
        for (int ks = 0; ks < 4; ks++) {
            const int c0 = ks*8 + tig;
            float a0[4], a1[4];
            int ra = wm*32 + gid;
            a0[0] = ap[ ra      *SA + c0    ];
            a0[1] = ap[(ra+8)   *SA + c0    ];
            a0[2] = ap[ ra      *SA + c0 + 4];
            a0[3] = ap[(ra+8)   *SA + c0 + 4];
            a1[0] = ap[(ra+16)  *SA + c0    ];
            a1[1] = ap[(ra+24)  *SA + c0    ];
            a1[2] = ap[(ra+16)  *SA + c0 + 4];
            a1[3] = ap[(ra+24)  *SA + c0 + 4];
#pragma unroll
            for (int nt = 0; nt < 8; nt++) {
                float b[2];
                int nb = wn*64 + nt*8 + gid;
                b[0] = bp[(ks*8 + tig    )*SB + nb];
                b[1] = bp[(ks*8 + tig + 4)*SB + nb];
                mma_tf32(acc[0][nt], a0, b);
                mma_tf32(acc[1][nt], a1, b);
            }
        }
    }

#pragma unroll
    for (int im = 0; im < 2; im++) {
        int rr = row0 + wm*32 + im*16 + gid;
#pragma unroll
        for (int nt = 0; nt < 8; nt++) {
            int cc = col0 + wn*64 + nt*8 + 2*tig;
            float bx = g_beff[cc], by = g_beff[cc+1];
            *(float2*)(out + (size_t)rr*DM + cc) =
                make_float2(acc[im][nt][0] + bx, acc[im][nt][1] + by);
            *(float2*)(out + (size_t)(rr+8)*DM + cc) =
                make_float2(acc[im][nt][2] + bx, acc[im][nt][3] + by);
        }
    }
}

// ---------------------------------------------------------------------------
extern "C" void kernel_launch(void* const* d_in, const int* in_sizes, int n_in,
                              void* d_out, int out_size)
{
    (void)in_sizes; (void)n_in; (void)out_size;
    const float* h    = (const float*)d_in[0];
    const float* Wdq  = (const float*)d_in[1];
    const float* bdq  = (const float*)d_in[2];
    const float* Wuq  = (const float*)d_in[3];
    const float* buq  = (const float*)d_in[4];
    const float* Wdkv = (const float*)d_in[5];
    const float* bdkv = (const float*)d_in[6];
    const float* Wuk  = (const float*)d_in[7];
    const float* buk  = (const float*)d_in[8];   (void)buk; // cancels in softmax
    const float* Wuv  = (const float*)d_in[9];
    const float* buv  = (const float*)d_in[10];
    const float* Wqr  = (const float*)d_in[11];
    const float* bqr  = (const float*)d_in[12];
    const float* Wkr  = (const float*)d_in[13];
    const float* bkr  = (const float*)d_in[14];
    const float* Wo   = (const float*)d_in[15];
    const float* bo   = (const float*)d_in[16];
    float* out = (float*)d_out;

    cudaFuncSetAttribute(attn_kernel, cudaFuncAttributeMaxDynamicSharedMemorySize,
                         ATTN_SMEM_FLOATS * (int)sizeof(float));
    cudaFuncSetAttribute(out_proj_kernel, cudaFuncAttributeMaxDynamicSharedMemorySize,
                         OUT_SMEM_FLOATS * (int)sizeof(float));
    cudaFuncSetAttribute(down_proj_kernel, cudaFuncAttributeMaxDynamicSharedMemorySize,
                         DOWN_SMEM_FLOATS * (int)sizeof(float));

    // attn is the 4th launch (ncu capture window)
    prep_kernel<<<116, 256>>>(Wuq, buq, Wuk, Wdq, Wdkv, Wkr, Wuv, buv, Wo, bo);
    down_proj_kernel<<<BS_/64, 256, DOWN_SMEM_FLOATS * sizeof(float)>>>(h, bdq, bdkv, bkr);
    q_proj_kernel<<<dim3(BS_/64, H_), 256>>>(Wqr, bqr);
    attn_kernel<<<dim3(S_/256, B_*H_), 512, ATTN_SMEM_FLOATS * sizeof(float)>>>();
    out_proj_kernel<<<dim3(DM/128, BS_/128), 256, OUT_SMEM_FLOATS * sizeof(float)>>>(out);
}

// round 17
// speedup vs baseline: 1.0194x; 1.0194x over previous
#include <cuda_runtime.h>
#include <math.h>
#include <stdint.h>

#define B_   4
#define S_   2048
#define DM   1024
#define H_   8
#define DK   128
#define DC   32
#define DHR  32
#define BS_  (B_*S_)        // 8192

// ---------------- scratch (device globals) ----------------------------------
__device__ float g_cq  [BS_*DC];               // fp32
__device__ float g_kt  [BS_*64];               // K~ pair-permuted cols, rounded
__device__ float g_cvT [BS_*DC];               // C^T tiles [tile][col][64 rows perm]
__device__ float g_qt  [(size_t)B_*H_*S_*64];  // Q~ permuted, PRE-SCALED by scale*log2e, rounded
__device__ float g_ot  [(size_t)BS_*H_*32];    // O~ [B,S,H*32], rounded
__device__ float g_M   [H_*DC*DC];
__device__ float g_m   [H_*DC];
__device__ float g_weff[256*DM];               // rounded
__device__ float g_beff[DM];
__device__ float g_wdown[1024*96];             // [Wdq|Wdkv|Wkr], rounded

// ---------------- helpers ----------------------------------------------------
__device__ __forceinline__ float to_tf32(float x) {
    uint32_t u;
    asm("cvt.rna.tf32.f32 %0, %1;" : "=r"(u) : "f"(x));
    return __uint_as_float(u);
}
__device__ __forceinline__ int perm8(int c) {
    return ((c & 3) << 1) | ((c >> 2) & 1);
}
__device__ __forceinline__ int ppos(int c) {
    return (c & ~7) | perm8(c & 7);
}
__device__ __forceinline__ void mma_tf32(float* d, const float* a, const float* b) {
    asm("mma.sync.aligned.m16n8k8.row.col.f32.tf32.tf32.f32 "
        "{%0,%1,%2,%3}, {%4,%5,%6,%7}, {%8,%9}, {%0,%1,%2,%3};"
        : "+f"(d[0]), "+f"(d[1]), "+f"(d[2]), "+f"(d[3])
        : "r"(__float_as_uint(a[0])), "r"(__float_as_uint(a[1])),
          "r"(__float_as_uint(a[2])), "r"(__float_as_uint(a[3])),
          "r"(__float_as_uint(b[0])), "r"(__float_as_uint(b[1])));
}
__device__ __forceinline__ void cp_async16(uint32_t saddr, const void* gptr) {
    asm volatile("cp.async.cg.shared.global [%0], [%1], 16;"
                 :: "r"(saddr), "l"(gptr));
}
#define CP_COMMIT()  asm volatile("cp.async.commit_group;")
#define CP_WAIT1()   asm volatile("cp.async.wait_group 1;")

// ---------------------------------------------------------------------------
// Launch 1: merged prep. blocks 0..7: M_h,m_h (smem-staged); 8..19: wdown;
// 20..83: W_eff; 84..115: b_eff.
// ---------------------------------------------------------------------------
__global__ void __launch_bounds__(256) prep_kernel(
    const float* __restrict__ Wuq, const float* __restrict__ buq,
    const float* __restrict__ Wuk,
    const float* __restrict__ Wdq, const float* __restrict__ Wdkv,
    const float* __restrict__ Wkr,
    const float* __restrict__ Wuv, const float* __restrict__ buv,
    const float* __restrict__ Wo,  const float* __restrict__ bo)
{
    const int tid = threadIdx.x;
    const int bx  = blockIdx.x;
    if (bx < 8) {
        __shared__ float wq_s[32*128];
        __shared__ float wk_s[32*128];
        const int h = bx;
#pragma unroll
        for (int i = 0; i < 4; i++) {
            int idx4 = tid + i*256;
            int r = idx4 >> 5, c4 = idx4 & 31;
            *(float4*)(wq_s + r*128 + c4*4) =
                *(const float4*)(Wuq + (size_t)r*DM + h*DK + c4*4);
            *(float4*)(wk_s + r*128 + c4*4) =
                *(const float4*)(Wuk + (size_t)r*DM + h*DK + c4*4);
        }
        __syncthreads();
        for (int idx = tid; idx < DC*DC; idx += 256) {
            int c = idx >> 5, i = idx & 31;
            float s = 0.f;
#pragma unroll 8
            for (int d = 0; d < DK; d++) s += wq_s[c*128 + d]*wk_s[i*128 + d];
            g_M[h*DC*DC + idx] = s;
        }
        if (tid < DC) {
            float s = 0.f;
#pragma unroll 8
            for (int d = 0; d < DK; d++) s += buq[h*DK + d]*wk_s[tid*128 + d];
            g_m[h*DC + tid] = s;
        }
    } else if (bx < 20) {
        int base = (bx - 8)*8192 + tid;
#pragma unroll
        for (int i = 0; i < 32; i++) {
            int idx = base + i*256;
            int k = idx / 96, c = idx - 96*k;
            float v;
            if (c < 32)      v = Wdq [k*32 + c];
            else if (c < 64) v = Wdkv[k*32 + (c-32)];
            else             v = Wkr [k*32 + (c-64)];
            g_wdown[idx] = to_tf32(v);
        }
    } else if (bx < 84) {
        const int h = (bx-20) >> 3, jt = (bx-20) & 7;
        const int i = tid >> 3, jg = tid & 7;
        const int j0 = jt*128 + jg*16;
        float acc[16];
#pragma unroll
        for (int k = 0; k < 16; k++) acc[k] = 0.f;
        for (int d = 0; d < DK; d++) {
            float wuv = Wuv[i*DM + h*DK + d];
            const float* wo = Wo + (size_t)(h*DK + d)*DM + j0;
#pragma unroll
            for (int k = 0; k < 16; k++) acc[k] += wuv*wo[k];
        }
#pragma unroll
        for (int k = 0; k < 16; k++)
            g_weff[(size_t)(h*32 + i)*DM + j0 + k] = to_tf32(acc[k]);
    } else {
        __shared__ float red[8][32];
        const int j0 = (bx - 84)*32;
        const int jj = tid & 31, ks = tid >> 5;
        float s = 0.f;
        const int k0 = ks*128;
        for (int k = 0; k < 128; k++)
            s += buv[k0 + k]*Wo[(size_t)(k0 + k)*DM + j0 + jj];
        red[ks][jj] = s;
        __syncthreads();
        if (ks == 0) {
            float acc = bo[j0 + jj];
#pragma unroll
            for (int r = 0; r < 8; r++) acc += red[r][jj];
            g_beff[j0 + jj] = acc;
        }
    }
}

// ---------------------------------------------------------------------------
// Launch 2: down projections via tf32 mma, 3-stage pipeline, 64-row tiles.
// ---------------------------------------------------------------------------
#define DSA 36
#define DSB 104
#define DABUF (64*DSA)
#define DBBUF (32*DSB)
#define DOWN_SMEM_FLOATS (3*DABUF + 3*DBBUF)

__global__ void __launch_bounds__(256) down_proj_kernel(
    const float* __restrict__ h,
    const float* __restrict__ bdq, const float* __restrict__ bdkv,
    const float* __restrict__ bkr)
{
    extern __shared__ float sm[];
    float* a_s = sm;
    float* b_s = sm + 3*DABUF;
    const uint32_t smb = (uint32_t)__cvta_generic_to_shared(sm);

    const int tid  = threadIdx.x;
    const int lane = tid & 31;
    const int warp = tid >> 5;
    const int gid  = lane >> 2, tig = lane & 3;
    const int wm = warp >> 1, wn = warp & 1;
    const int row0 = blockIdx.x * 64;

    auto issue_ab = [&](int s, int kc) {
        const uint32_t adst = smb + (uint32_t)(s*DABUF)*4u;
        const uint32_t bdst = smb + (uint32_t)(3*DABUF + s*DBBUF)*4u;
#pragma unroll
        for (int i = 0; i < 2; i++) {
            int idx4 = tid + i*256;
            int r = idx4 >> 3, c4 = idx4 & 7;
            cp_async16(adst + (uint32_t)(r*DSA + c4*4)*4u,
                       h + (size_t)(row0+r)*DM + kc*32 + c4*4);
        }
#pragma unroll
        for (int i = 0; i < 3; i++) {
            int idx4 = tid + i*256;
            int r = idx4 / 24, cc = idx4 - 24*r;
            cp_async16(bdst + (uint32_t)(r*DSB + cc*4)*4u,
                       g_wdown + (size_t)(kc*32+r)*96 + cc*4);
        }
    };

    float acc[6][4];
#pragma unroll
    for (int n = 0; n < 6; n++)
#pragma unroll
        for (int j = 0; j < 4; j++) acc[n][j] = 0.f;

    issue_ab(0, 0); CP_COMMIT();
    issue_ab(1, 1); CP_COMMIT();

    for (int kc = 0; kc < 32; kc++) {
        CP_WAIT1();
        __syncthreads();
        if (kc + 2 < 32) issue_ab((kc + 2) % 3, kc + 2);
        CP_COMMIT();
        const float* ap = a_s + (kc % 3)*DABUF;
        const float* bp = b_s + (kc % 3)*DBBUF;

#pragma unroll
        for (int ks = 0; ks < 4; ks++) {
            const int c0 = ks*8 + tig;
            float a0[4];
            int ra = wm*16 + gid;
            a0[0] = ap[ ra      *DSA + c0    ];
            a0[1] = ap[(ra+8)   *DSA + c0    ];
            a0[2] = ap[ ra      *DSA + c0 + 4];
            a0[3] = ap[(ra+8)   *DSA + c0 + 4];
#pragma unroll
            for (int nt = 0; nt < 6; nt++) {
                float b[2];
                int nb = wn*48 + nt*8 + gid;
                b[0] = bp[(ks*8 + tig    )*DSB + nb];
                b[1] = bp[(ks*8 + tig + 4)*DSB + nb];
                mma_tf32(acc[nt], a0, b);
            }
        }
    }

    {
        int rbase = row0 + wm*16 + gid;
#pragma unroll
        for (int nt = 0; nt < 6; nt++) {
            int cc = wn*48 + nt*8 + 2*tig;
#pragma unroll
            for (int half = 0; half < 2; half++) {
                int rr = rbase + half*8;
#pragma unroll
                for (int e = 0; e < 2; e++) {
                    int col = cc + e;
                    float v = acc[nt][half*2 + e];
                    if (col < 32) {
                        g_cq[rr*32 + col] = v + bdq[col];
                    } else if (col < 64) {
                        float cv = to_tf32(v + bdkv[col-32]);
                        g_kt[rr*64 + ppos(col-32)] = cv;
                        int t = rr >> 6, lr = rr & 63;
                        g_cvT[((size_t)t*32 + (col-32))*64 + ppos(lr)] = cv;
                    } else {
                        g_kt[rr*64 + 32 + ppos(col-64)] =
                            to_tf32(v + bkr[col-64]);
                    }
                }
            }
        }
    }
}

// ---------------------------------------------------------------------------
// Launch 3: Q~ = (scale*log2e) * [c_q@M_h+m_h | c_q@W_QR_h+b_QR_h], permuted.
// R15 conflict-free scalar form.
// ---------------------------------------------------------------------------
__global__ void __launch_bounds__(256) q_proj_kernel(
    const float* __restrict__ Wqr, const float* __restrict__ bqr)
{
    __shared__ float w_s[32*64];
    __shared__ float c_s[64*32];
    __shared__ float bias_s[64];

    const int tid  = threadIdx.x;
    const int hh   = blockIdx.y;
    const int row0 = blockIdx.x * 64;
    const float pres = 0.07905694150420948f * 1.4426950408889634f; // scale*log2e

#pragma unroll
    for (int i = 0; i < 8; i++) {
        int idx = tid + i*256;
        int k = idx >> 6, c = idx & 63;
        w_s[idx] = (c < 32) ? g_M[hh*DC*DC + k*32 + c]
                            : Wqr[k*256 + hh*32 + (c-32)];
    }
    if (tid < 64)
        bias_s[tid] = (tid < 32) ? g_m[hh*DC + tid] : bqr[hh*32 + tid - 32];
#pragma unroll
    for (int i = 0; i < 8; i++) {
        int idx = tid + i*256;
        c_s[idx] = g_cq[row0*32 + idx];
    }
    __syncthreads();

    const int col = tid & 63, rg = tid >> 6;
    const int pcol = ppos(col);
    for (int rr = 0; rr < 16; rr++) {
        int r = rg*16 + rr;
        float acc = bias_s[col];
#pragma unroll
        for (int k = 0; k < 32; k++) acc += c_s[r*32 + k]*w_s[k*64 + col];
        int row = row0 + r;
        int bb = row >> 11, ss = row & 2047;
        g_qt[((size_t)(bb*H_ + hh)*S_ + ss)*64 + pcol] = to_tf32(acc * pres);
    }
}

// ---------------------------------------------------------------------------
// Launch 4 (PROFILED): absorbed flash attention, exp2-based softmax.
// ---------------------------------------------------------------------------
#define SKT 72
#define SCT 72
#define KT_FL (64*SKT)
#define CT_FL (32*SCT)
#define QBUF_FL (256*SKT)
#define ATTN_SMEM_FLOATS (QBUF_FL + 3*KT_FL + 3*CT_FL)

__global__ void __launch_bounds__(512, 1) attn_kernel()
{
    extern __shared__ float sm[];
    float* qbuf = sm;
    float* kbuf = sm + QBUF_FL;
    float* cbuf = kbuf + 3*KT_FL;
    const uint32_t smb = (uint32_t)__cvta_generic_to_shared(sm);

    const int tid  = threadIdx.x;
    const int lane = tid & 31;
    const int warp = tid >> 5;
    const int gid  = lane >> 2;
    const int tig  = lane & 3;
    const int bh   = blockIdx.y;
    const int bb   = bh >> 3, hh = bh & 7;
    const int q0   = blockIdx.x * 256;

    const float* qg = g_qt + ((size_t)bh*S_ + q0)*64;
    const float* kg = g_kt + (size_t)bb*S_*64;
    const float* cg = g_cvT + (size_t)bb*(S_/64)*2048;

#pragma unroll
    for (int i = 0; i < 8; i++) {
        int idx4 = tid + i*512;
        int r = idx4 >> 4, c4 = idx4 & 15;
        float4 v = *(const float4*)(qg + (size_t)r*64 + c4*4);
        *(float4*)(qbuf + r*SKT + c4*4) = v;
    }
    __syncthreads();

    const int r0 = warp*16 + gid;
    float qf[8][4];
#pragma unroll
    for (int kb = 0; kb < 8; kb++) {
        float2 f0 = *(const float2*)(qbuf +  r0   *SKT + kb*8 + 2*tig);
        float2 f1 = *(const float2*)(qbuf + (r0+8)*SKT + kb*8 + 2*tig);
        qf[kb][0] = f0.x; qf[kb][1] = f1.x; qf[kb][2] = f0.y; qf[kb][3] = f1.y;
    }

    auto issue_kv = [&](int s, int t) {
        const float* ksrc = kg + (size_t)t*64*64;
        const float* csrc = cg + (size_t)t*2048;
        const uint32_t kdst = smb + (uint32_t)(QBUF_FL + s*KT_FL)*4u;
        const uint32_t cdst = smb + (uint32_t)(QBUF_FL + 3*KT_FL + s*CT_FL)*4u;
#pragma unroll
        for (int i = 0; i < 2; i++) {
            int idx4 = tid + i*512;
            int r = idx4 >> 4, c4 = idx4 & 15;
            cp_async16(kdst + (uint32_t)(r*SKT + c4*4)*4u, ksrc + r*64 + c4*4);
        }
        {
            int c = tid >> 4, rg = tid & 15;
            cp_async16(cdst + (uint32_t)(c*SCT + rg*4)*4u, csrc + c*64 + rg*4);
        }
    };

    issue_kv(0, 0); CP_COMMIT();
    issue_kv(1, 1); CP_COMMIT();

    float m0 = -1e30f, m1 = -1e30f, l0 = 0.f, l1 = 0.f;
    float o[4][4];
#pragma unroll
    for (int i = 0; i < 4; i++)
#pragma unroll
        for (int j = 0; j < 4; j++) o[i][j] = 0.f;

    const int srcA = (lane & ~3) + (tig >> 1);
    const int srcB = srcA + 2;
    const bool odd = (tig & 1);

    for (int kt = 0; kt < S_/64; kt++) {
        CP_WAIT1();
        __syncthreads();
        if (kt + 2 < S_/64) issue_kv((kt + 2) % 3, kt + 2);
        CP_COMMIT();
        const float* ks = kbuf + (kt % 3)*KT_FL;
        const float* cs = cbuf + (kt % 3)*CT_FL;

        float sa[8][4];
#pragma unroll
        for (int n = 0; n < 8; n++)
#pragma unroll
            for (int j = 0; j < 4; j++) sa[n][j] = 0.f;

#pragma unroll
        for (int kb = 0; kb < 8; kb++) {
#pragma unroll
            for (int nt = 0; nt < 8; nt++) {
                float2 bv = *(const float2*)(ks + (nt*8+gid)*SKT + kb*8 + 2*tig);
                float b[2] = {bv.x, bv.y};
                mma_tf32(sa[nt], qf[kb], b);
            }
        }

        float mx0 = -1e30f, mx1 = -1e30f;
#pragma unroll
        for (int n = 0; n < 8; n++) {
            mx0 = fmaxf(mx0, fmaxf(sa[n][0], sa[n][1]));
            mx1 = fmaxf(mx1, fmaxf(sa[n][2], sa[n][3]));
        }
        mx0 = fmaxf(mx0, __shfl_xor_sync(0xffffffffu, mx0, 1));
        mx0 = fmaxf(mx0, __shfl_xor_sync(0xffffffffu, mx0, 2));
        mx1 = fmaxf(mx1, __shfl_xor_sync(0xffffffffu, mx1, 1));
        mx1 = fmaxf(mx1, __shfl_xor_sync(0xffffffffu, mx1, 2));

        float nm0 = fmaxf(m0, mx0), nm1 = fmaxf(m1, mx1);
        float al0 = exp2f(m0 - nm0), al1 = exp2f(m1 - nm1);
        m0 = nm0; m1 = nm1;

#pragma unroll
        for (int n = 0; n < 4; n++) {
            o[n][0] *= al0; o[n][1] *= al0;
            o[n][2] *= al1; o[n][3] *= al1;
        }

        float rs0 = 0.f, rs1 = 0.f;
#pragma unroll
        for (int kb = 0; kb < 8; kb++) {
            float p00 = exp2f(sa[kb][0] - nm0);
            float p01 = exp2f(sa[kb][1] - nm0);
            float p10 = exp2f(sa[kb][2] - nm1);
            float p11 = exp2f(sa[kb][3] - nm1);
            rs0 += p00 + p01; rs1 += p10 + p11;

            float q00A = __shfl_sync(0xffffffffu, p00, srcA);
            float q01A = __shfl_sync(0xffffffffu, p01, srcA);
            float q00B = __shfl_sync(0xffffffffu, p00, srcB);
            float q01B = __shfl_sync(0xffffffffu, p01, srcB);
            float q10A = __shfl_sync(0xffffffffu, p10, srcA);
            float q11A = __shfl_sync(0xffffffffu, p11, srcA);
            float q10B = __shfl_sync(0xffffffffu, p10, srcB);
            float q11B = __shfl_sync(0xffffffffu, p11, srcB);

            float a[4];
            a[0] = to_tf32(odd ? q01A : q00A);
            a[1] = to_tf32(odd ? q11A : q10A);
            a[2] = to_tf32(odd ? q01B : q00B);
            a[3] = to_tf32(odd ? q11B : q10B);
#pragma unroll
            for (int nt = 0; nt < 4; nt++) {
                float2 bv = *(const float2*)(cs + (nt*8+gid)*SCT + kb*8 + 2*tig);
                float b[2] = {bv.x, bv.y};
                mma_tf32(o[nt], a, b);
            }
        }
        rs0 += __shfl_xor_sync(0xffffffffu, rs0, 1);
        rs0 += __shfl_xor_sync(0xffffffffu, rs0, 2);
        rs1 += __shfl_xor_sync(0xffffffffu, rs1, 1);
        rs1 += __shfl_xor_sync(0xffffffffu, rs1, 2);
        l0 = l0*al0 + rs0; l1 = l1*al1 + rs1;
    }

    const float inv0 = 1.f / l0, inv1 = 1.f / l1;
    const int s0 = q0 + r0;
    float* op0 = g_ot + ((size_t)(bb*S_ + s0    )*H_ + hh)*32;
    float* op1 = g_ot + ((size_t)(bb*S_ + s0 + 8)*H_ + hh)*32;
#pragma unroll
    for (int nt = 0; nt < 4; nt++) {
        int col = nt*8 + 2*tig;
        *(float2*)(op0 + col) = make_float2(to_tf32(o[nt][0]*inv0), to_tf32(o[nt][1]*inv0));
        *(float2*)(op1 + col) = make_float2(to_tf32(o[nt][2]*inv1), to_tf32(o[nt][3]*inv1));
    }
}

// ---------------------------------------------------------------------------
// Launch 5: out = O~[8192x256] @ W_eff[256x1024] + b_eff, 3-stage pipeline
// ---------------------------------------------------------------------------
#define SA 36
#define SB 136
#define ABUF_FL (128*SA)
#define BBUF_FL (32*SB)
#define OUT_SMEM_FLOATS (3*ABUF_FL + 3*BBUF_FL)

__global__ void __launch_bounds__(256) out_proj_kernel(float* __restrict__ out)
{
    extern __shared__ float sm[];
    float* a_s = sm;
    float* b_s = sm + 3*ABUF_FL;
    const uint32_t smb = (uint32_t)__cvta_generic_to_shared(sm);

    const int tid  = threadIdx.x;
    const int lane = tid & 31;
    const int warp = tid >> 5;
    const int gid  = lane >> 2, tig = lane & 3;
    const int wm = warp >> 1, wn = warp & 1;
    const int col0 = blockIdx.x * 128;
    const int row0 = blockIdx.y * 128;

    auto issue_ab = [&](int s, int kc) {
        const uint32_t adst = smb + (uint32_t)(s*ABUF_FL)*4u;
        const uint32_t bdst = smb + (uint32_t)(3*ABUF_FL + s*BBUF_FL)*4u;
#pragma unroll
        for (int i = 0; i < 4; i++) {
            int idx4 = tid + i*256;
            int r = idx4 >> 3, c4 = idx4 & 7;
            cp_async16(adst + (uint32_t)(r*SA + c4*4)*4u,
                       g_ot + (size_t)(row0+r)*256 + kc*32 + c4*4);
        }
#pragma unroll
        for (int i = 0; i < 4; i++) {
            int idx4 = tid + i*256;
            int r = idx4 >> 5, c4 = idx4 & 31;
            cp_async16(bdst + (uint32_t)(r*SB + c4*4)*4u,
                       g_weff + (size_t)(kc*32+r)*DM + col0 + c4*4);
        }
    };

    float acc[2][8][4];
#pragma unroll
    for (int im = 0; im < 2; im++)
#pragma unroll
        for (int n = 0; n < 8; n++)
#pragma unroll
            for (int j = 0; j < 4; j++) acc[im][n][j] = 0.f;

    issue_ab(0, 0); CP_COMMIT();
    issue_ab(1, 1); CP_COMMIT();

    for (int kc = 0; kc < 8; kc++) {
        CP_WAIT1();
        __syncthreads();
        if (kc + 2 < 8) issue_ab((kc + 2) % 3, kc + 2);
        CP_COMMIT();
        const float* ap = a_s + (kc % 3)*ABUF_FL;
        const float* bp = b_s + (kc % 3)*BBUF_FL;

#pragma unroll
        for (int ks = 0; ks < 4; ks++) {
            const int c0 = ks*8 + tig;
            float a0[4], a1[4];
            int ra = wm*32 + gid;
            a0[0] = ap[ ra      *SA + c0    ];
            a0[1] = ap[(ra+8)   *SA + c0    ];
            a0[2] = ap[ ra      *SA + c0 + 4];
            a0[3] = ap[(ra+8)   *SA + c0 + 4];
            a1[0] = ap[(ra+16)  *SA + c0    ];
            a1[1] = ap[(ra+24)  *SA + c0    ];
            a1[2] = ap[(ra+16)  *SA + c0 + 4];
            a1[3] = ap[(ra+24)  *SA + c0 + 4];
#pragma unroll
            for (int nt = 0; nt < 8; nt++) {
                float b[2];
                int nb = wn*64 + nt*8 + gid;
                b[0] = bp[(ks*8 + tig    )*SB + nb];
                b[1] = bp[(ks*8 + tig + 4)*SB + nb];
                mma_tf32(acc[0][nt], a0, b);
                mma_tf32(acc[1][nt], a1, b);
            }
        }
    }

#pragma unroll
    for (int im = 0; im < 2; im++) {
        int rr = row0 + wm*32 + im*16 + gid;
#pragma unroll
        for (int nt = 0; nt < 8; nt++) {
            int cc = col0 + wn*64 + nt*8 + 2*tig;
            float bx = g_beff[cc], by = g_beff[cc+1];
            *(float2*)(out + (size_t)rr*DM + cc) =
                make_float2(acc[im][nt][0] + bx, acc[im][nt][1] + by);
            *(float2*)(out + (size_t)(rr+8)*DM + cc) =
                make_float2(acc[im][nt][2] + bx, acc[im][nt][3] + by);
        }
    }
}

// ---------------------------------------------------------------------------
extern "C" void kernel_launch(void* const* d_in, const int* in_sizes, int n_in,
                              void* d_out, int out_size)
{
    (void)in_sizes; (void)n_in; (void)out_size;
    const float* h    = (const float*)d_in[0];
    const float* Wdq  = (const float*)d_in[1];
    const float* bdq  = (const float*)d_in[2];
    const float* Wuq  = (const float*)d_in[3];
    const float* buq  = (const float*)d_in[4];
    const float* Wdkv = (const float*)d_in[5];
    const float* bdkv = (const float*)d_in[6];
    const float* Wuk  = (const float*)d_in[7];
    const float* buk  = (const float*)d_in[8];   (void)buk; // cancels in softmax
    const float* Wuv  = (const float*)d_in[9];
    const float* buv  = (const float*)d_in[10];
    const float* Wqr  = (const float*)d_in[11];
    const float* bqr  = (const float*)d_in[12];
    const float* Wkr  = (const float*)d_in[13];
    const float* bkr  = (const float*)d_in[14];
    const float* Wo   = (const float*)d_in[15];
    const float* bo   = (const float*)d_in[16];
    float* out = (float*)d_out;

    cudaFuncSetAttribute(attn_kernel, cudaFuncAttributeMaxDynamicSharedMemorySize,
                         ATTN_SMEM_FLOATS * (int)sizeof(float));
    cudaFuncSetAttribute(out_proj_kernel, cudaFuncAttributeMaxDynamicSharedMemorySize,
                         OUT_SMEM_FLOATS * (int)sizeof(float));
    cudaFuncSetAttribute(down_proj_kernel, cudaFuncAttributeMaxDynamicSharedMemorySize,
                         DOWN_SMEM_FLOATS * (int)sizeof(float));

    // attn is the 4th launch (ncu capture window)
    prep_kernel<<<116, 256>>>(Wuq, buq, Wuk, Wdq, Wdkv, Wkr, Wuv, buv, Wo, bo);
    down_proj_kernel<<<BS_/64, 256, DOWN_SMEM_FLOATS * sizeof(float)>>>(h, bdq, bdkv, bkr);
    q_proj_kernel<<<dim3(BS_/64, H_), 256>>>(Wqr, bqr);
    attn_kernel<<<dim3(S_/256, B_*H_), 512, ATTN_SMEM_FLOATS * sizeof(float)>>>();
    out_proj_kernel<<<dim3(DM/128, BS_/128), 256, OUT_SMEM_FLOATS * sizeof(float)>>>(out);
}